// round 1
// baseline (speedup 1.0000x reference)
#include <cuda_runtime.h>
#include <math.h>
#include <stdint.h>

#define NMAX 4096
#define SCALE_F 10.0f
#define EPS_F 1e-5f

__device__ float g_dist[(size_t)NMAX * NMAX];
__device__ float g_sq[NMAX];
__device__ unsigned char g_cam[NMAX];
__device__ float g_partial[NMAX];

#define INF_F __int_as_float(0x7f800000)

// ---------------------------------------------------------------------------
// Normalize camid (int64-or-int32) to uint8. Detection: if the first 128
// odd 32-bit words are all zero, the buffer is little-endian int64
// (values are 0..7, so high words are 0). P(false positive on int32) ~ 8^-128.
// ---------------------------------------------------------------------------
__global__ void prep_cam_kernel(const int* __restrict__ cam_raw, int n) {
    __shared__ int s_is64;
    if (threadIdx.x == 0) {
        int is64 = 1;
        int checks = n < 128 ? n : 128;
        for (int k = 0; k < checks; ++k) {
            if (cam_raw[2 * k + 1] != 0) { is64 = 0; break; }
        }
        s_is64 = is64;
    }
    __syncthreads();
    int is64 = s_is64;
    for (int j = threadIdx.x; j < n; j += blockDim.x) {
        int v = is64 ? cam_raw[2 * j] : cam_raw[j];
        g_cam[j] = (unsigned char)v;
    }
}

// ---------------------------------------------------------------------------
// Row squared norms: one warp per row, d multiple of 128 (d=256).
// ---------------------------------------------------------------------------
__global__ void sq_kernel(const float* __restrict__ feat, int n, int d) {
    int warp = (blockIdx.x * blockDim.x + threadIdx.x) >> 5;
    int lane = threadIdx.x & 31;
    if (warp >= n) return;
    const float* row = feat + (size_t)warp * d;
    float s = 0.f;
    for (int k = lane * 4; k < d; k += 32 * 4) {
        float4 v = *(const float4*)(row + k);
        s += v.x * v.x + v.y * v.y + v.z * v.z + v.w * v.w;
    }
#pragma unroll
    for (int off = 16; off; off >>= 1) s += __shfl_down_sync(0xffffffffu, s, off);
    if (lane == 0) g_sq[warp] = s;
}

// ---------------------------------------------------------------------------
// Distance GEMM: dist[i][j] = sqrt(max(sq[i]+sq[j]+eps-2*dot(fi,fj), 1e-12))
// 64x64 tile, BK=16, 256 threads, 4x4 micro-tile per thread.
// ---------------------------------------------------------------------------
#define BM 64
#define BK 16
#define LDA 68   // padded leading dim; multiple of 4 for float4 LDS alignment

__global__ void __launch_bounds__(256) dist_gemm_kernel(
        const float* __restrict__ feat, int n, int d) {
    __shared__ float As[BK][LDA];
    __shared__ float Bs[BK][LDA];

    int bi = blockIdx.y, bj = blockIdx.x;
    int t  = threadIdx.x;
    int lr = t >> 2;            // 0..63  : tile row to load
    int lc = (t & 3) << 2;      // 0,4,8,12 : k offset (float4)
    int tx = t & 15;            // micro-tile col group
    int ty = t >> 4;            // micro-tile row group

    const float* aBase = feat + (size_t)(bi * BM + lr) * d + lc;
    const float* bBase = feat + (size_t)(bj * BM + lr) * d + lc;

    float acc[4][4];
#pragma unroll
    for (int r = 0; r < 4; ++r)
#pragma unroll
        for (int c = 0; c < 4; ++c) acc[r][c] = 0.f;

    for (int k0 = 0; k0 < d; k0 += BK) {
        float4 av = *(const float4*)(aBase + k0);
        float4 bv = *(const float4*)(bBase + k0);
        __syncthreads();
        As[lc + 0][lr] = av.x; As[lc + 1][lr] = av.y;
        As[lc + 2][lr] = av.z; As[lc + 3][lr] = av.w;
        Bs[lc + 0][lr] = bv.x; Bs[lc + 1][lr] = bv.y;
        Bs[lc + 2][lr] = bv.z; Bs[lc + 3][lr] = bv.w;
        __syncthreads();
#pragma unroll
        for (int kk = 0; kk < BK; ++kk) {
            float4 a = *(const float4*)&As[kk][ty << 2];
            float4 b = *(const float4*)&Bs[kk][tx << 2];
            acc[0][0] += a.x * b.x; acc[0][1] += a.x * b.y;
            acc[0][2] += a.x * b.z; acc[0][3] += a.x * b.w;
            acc[1][0] += a.y * b.x; acc[1][1] += a.y * b.y;
            acc[1][2] += a.y * b.z; acc[1][3] += a.y * b.w;
            acc[2][0] += a.z * b.x; acc[2][1] += a.z * b.y;
            acc[2][2] += a.z * b.z; acc[2][3] += a.z * b.w;
            acc[3][0] += a.w * b.x; acc[3][1] += a.w * b.y;
            acc[3][2] += a.w * b.z; acc[3][3] += a.w * b.w;
        }
    }

    int i0 = bi * BM + (ty << 2);
    int j0 = bj * BM + (tx << 2);
    float sqi[4], sqj[4];
#pragma unroll
    for (int r = 0; r < 4; ++r) sqi[r] = g_sq[i0 + r];
#pragma unroll
    for (int c = 0; c < 4; ++c) sqj[c] = g_sq[j0 + c];

#pragma unroll
    for (int r = 0; r < 4; ++r) {
        float4 o;
        float* op = &o.x;
#pragma unroll
        for (int c = 0; c < 4; ++c) {
            float v = sqi[r] + sqj[c] + EPS_F - 2.0f * acc[r][c];
            v = sqrtf(fmaxf(v, 1e-12f));
            if (i0 + r == j0 + c) v = sqrtf(EPS_F);  // exact self-distance
            op[c] = v;
        }
        *(float4*)&g_dist[(size_t)(i0 + r) * n + j0] = o;
    }
}

// ---------------------------------------------------------------------------
// Per-row selection + logsumexp. One CTA (256 threads) per row.
//   Per set (intra want=1 K=4 m=40 | inter want=0 K=6 m=6):
//     K rounds of min+knockout (set chosen element to +inf), one more min -> dK
//     then fixed-order sum of exp(10*(dK - d)) over masked elements
//     term = max(10*(d0-dK) + log(sum) + margin, 0)
// ---------------------------------------------------------------------------
__global__ void __launch_bounds__(256) row_kernel(int n) {
    __shared__ float sd[NMAX];
    __shared__ unsigned char sc[NMAX];
    __shared__ float s_wv[8];
    __shared__ int   s_wj[8];
    __shared__ float s_bv;
    __shared__ int   s_bj;
    __shared__ float s_sum;

    int i   = blockIdx.x;
    int tid = threadIdx.x;
    const float* drow = g_dist + (size_t)i * n;

    for (int j4 = tid * 4; j4 < n; j4 += 256 * 4)
        *(float4*)&sd[j4] = *(const float4*)&drow[j4];
    for (int j = tid; j < n / 4; j += 256)
        ((unsigned int*)sc)[j] = ((const unsigned int*)g_cam)[j];
    int mycam = g_cam[i];
    __syncthreads();

    float loss = 0.f;
#pragma unroll
    for (int pass = 0; pass < 2; ++pass) {
        int   want   = (pass == 0) ? 1 : 0;
        int   K      = (pass == 0) ? 4 : 6;
        float margin = (pass == 0) ? 40.f : 6.f;

        float d0 = INF_F, dK = INF_F;
        for (int r = 0; r <= K; ++r) {
            float bv = INF_F;
            int   bj = 0x7fffffff;
            for (int j = tid; j < n; j += 256) {
                if ((sc[j] == mycam) == want) {
                    float v = sd[j];
                    if (v < bv) { bv = v; bj = j; }
                }
            }
#pragma unroll
            for (int off = 16; off; off >>= 1) {
                float ov = __shfl_down_sync(0xffffffffu, bv, off);
                int   oj = __shfl_down_sync(0xffffffffu, bj, off);
                if (ov < bv || (ov == bv && oj < bj)) { bv = ov; bj = oj; }
            }
            if ((tid & 31) == 0) { s_wv[tid >> 5] = bv; s_wj[tid >> 5] = bj; }
            __syncthreads();
            if (tid == 0) {
                float fv = s_wv[0]; int fj = s_wj[0];
                for (int w = 1; w < 8; ++w)
                    if (s_wv[w] < fv || (s_wv[w] == fv && s_wj[w] < fj)) {
                        fv = s_wv[w]; fj = s_wj[w];
                    }
                s_bv = fv; s_bj = fj;
                if (r < K && fj < n) sd[fj] = INF_F;  // knockout
            }
            __syncthreads();
            if (r == 0) d0 = s_bv;
            if (r == K) dK = s_bv;
            __syncthreads();  // protect s_bv/s_wv before next round rewrites
        }

        float term = 0.f;
        if (isfinite(dK)) {   // uniform per block
            float s = 0.f;
            for (int j = tid; j < n; j += 256) {
                if ((sc[j] == mycam) == want)
                    s += expf(SCALE_F * (dK - sd[j]));  // knocked -> exp(-inf)=0
            }
#pragma unroll
            for (int off = 16; off; off >>= 1)
                s += __shfl_down_sync(0xffffffffu, s, off);
            if ((tid & 31) == 0) s_wv[tid >> 5] = s;
            __syncthreads();
            if (tid == 0) {
                float tot = 0.f;
                for (int w = 0; w < 8; ++w) tot += s_wv[w];
                s_sum = tot;
            }
            __syncthreads();
            term = fmaxf(SCALE_F * (d0 - dK) + logf(s_sum) + margin, 0.f);
            __syncthreads();
        }
        loss += (pass == 0) ? term : 0.5f * term;
    }
    if (tid == 0) g_partial[i] = loss;
}

// ---------------------------------------------------------------------------
// Deterministic fixed-order final reduction.
// ---------------------------------------------------------------------------
__global__ void final_kernel(int n, float* __restrict__ out) {
    __shared__ float sh[256];
    float s = 0.f;
    for (int j = threadIdx.x; j < n; j += 256) s += g_partial[j];
    sh[threadIdx.x] = s;
    __syncthreads();
    for (int st = 128; st; st >>= 1) {
        if (threadIdx.x < st) sh[threadIdx.x] += sh[threadIdx.x + st];
        __syncthreads();
    }
    if (threadIdx.x == 0) out[0] = sh[0] / (float)n;
}

// ---------------------------------------------------------------------------
extern "C" void kernel_launch(void* const* d_in, const int* in_sizes, int n_in,
                              void* d_out, int out_size) {
    const float* feat = (const float*)d_in[0];
    const int*   cam  = (const int*)d_in[1];
    int n = in_sizes[1];
    int d = in_sizes[0] / n;

    prep_cam_kernel<<<1, 256>>>(cam, n);
    sq_kernel<<<(n * 32 + 255) / 256, 256>>>(feat, n, d);
    dim3 grid(n / BM, n / BM);
    dist_gemm_kernel<<<grid, 256>>>(feat, n, d);
    row_kernel<<<n, 256>>>(n);
    final_kernel<<<1, 256>>>(n, (float*)d_out);
}

// round 3
// speedup vs baseline: 2.3949x; 2.3949x over previous
#include <cuda_runtime.h>
#include <cuda_bf16.h>
#include <math.h>
#include <stdint.h>

#define NMAX 4096
#define DMAX 256
#define KPACK 768              // [hi|hi|lo] / [hi|lo|hi]
#define SCALE_F 10.0f
#define EPS_F 1e-5f
#define INF_F __int_as_float(0x7f800000)

__device__ float g_dist[(size_t)NMAX * NMAX];
__device__ float g_sq[NMAX];
__device__ unsigned char g_cam[NMAX];
__device__ float g_partial[NMAX];
__device__ __nv_bfloat16 g_pa[(size_t)NMAX * KPACK];
__device__ __nv_bfloat16 g_pb[(size_t)NMAX * KPACK];

__device__ __forceinline__ uint32_t smem_to_u32(const void* p) {
    uint32_t a;
    asm("{ .reg .u64 t; cvta.to.shared.u64 t, %1; cvt.u32.u64 %0, t; }"
        : "=r"(a) : "l"(p));
    return a;
}

#define LDMATRIX_X4(R, addr) \
    asm volatile("ldmatrix.sync.aligned.m8n8.x4.shared.b16 {%0,%1,%2,%3}, [%4];" \
        : "=r"((R)[0]), "=r"((R)[1]), "=r"((R)[2]), "=r"((R)[3]) : "r"(addr))
#define LDMATRIX_X2(R, addr) \
    asm volatile("ldmatrix.sync.aligned.m8n8.x2.shared.b16 {%0,%1}, [%2];" \
        : "=r"((R)[0]), "=r"((R)[1]) : "r"(addr))
#define MMA_BF16(D, A, B) \
    asm volatile("mma.sync.aligned.m16n8k16.row.col.f32.bf16.bf16.f32 " \
        "{%0,%1,%2,%3}, {%4,%5,%6,%7}, {%8,%9}, {%0,%1,%2,%3};" \
        : "+f"((D)[0]), "+f"((D)[1]), "+f"((D)[2]), "+f"((D)[3]) \
        : "r"((A)[0]), "r"((A)[1]), "r"((A)[2]), "r"((A)[3]), \
          "r"((B)[0]), "r"((B)[1]))
#define CP_ASYNC16(dst, src) \
    asm volatile("cp.async.cg.shared.global [%0], [%1], 16;" \
        :: "r"(dst), "l"(src))
#define CP_COMMIT() asm volatile("cp.async.commit_group;")
#define CP_WAIT(N)  asm volatile("cp.async.wait_group %0;" :: "n"(N))

// ===========================================================================
// camid normalization (int64-or-int32 -> uint8)
// ===========================================================================
__global__ void prep_cam_kernel(const int* __restrict__ cam_raw, int n) {
    __shared__ int s_is64;
    if (threadIdx.x == 0) {
        int is64 = 1;
        int checks = n < 128 ? n : 128;
        for (int k = 0; k < checks; ++k)
            if (cam_raw[2 * k + 1] != 0) { is64 = 0; break; }
        s_is64 = is64;
    }
    __syncthreads();
    int is64 = s_is64;
    for (int j = threadIdx.x; j < n; j += blockDim.x)
        g_cam[j] = (unsigned char)(is64 ? cam_raw[2 * j] : cam_raw[j]);
}

// ===========================================================================
// Row squared norms
// ===========================================================================
__global__ void sq_kernel(const float* __restrict__ feat, int n, int d) {
    int warp = (blockIdx.x * blockDim.x + threadIdx.x) >> 5;
    int lane = threadIdx.x & 31;
    if (warp >= n) return;
    const float* row = feat + (size_t)warp * d;
    float s = 0.f;
    for (int k = lane * 4; k < d; k += 32 * 4) {
        float4 v = *(const float4*)(row + k);
        s += v.x * v.x + v.y * v.y + v.z * v.z + v.w * v.w;
    }
#pragma unroll
    for (int off = 16; off; off >>= 1) s += __shfl_down_sync(0xffffffffu, s, off);
    if (lane == 0) g_sq[warp] = s;
}

// ===========================================================================
// Split f32 -> bf16 hi+lo, pack A'=[hi|hi|lo], B'=[hi|lo|hi] (K=768)
// ===========================================================================
__global__ void split_pack_kernel(const float* __restrict__ f, int n, int d) {
    int idx = blockIdx.x * blockDim.x + threadIdx.x;   // one per 2 elems
    int half_d = d >> 1;                               // 128
    if (idx >= n * half_d) return;
    int i  = idx / half_d;
    int k2 = idx - i * half_d;
    float2 x = ((const float2*)f)[idx];
    __nv_bfloat16 h0 = __float2bfloat16_rn(x.x);
    __nv_bfloat16 h1 = __float2bfloat16_rn(x.y);
    __nv_bfloat16 l0 = __float2bfloat16_rn(x.x - __bfloat162float(h0));
    __nv_bfloat16 l1 = __float2bfloat16_rn(x.y - __bfloat162float(h1));
    __nv_bfloat162 hh(h0, h1), ll(l0, l1);
    __nv_bfloat162* pa = (__nv_bfloat162*)(g_pa + (size_t)i * KPACK);
    __nv_bfloat162* pb = (__nv_bfloat162*)(g_pb + (size_t)i * KPACK);
    pa[k2] = hh; pa[128 + k2] = hh; pa[256 + k2] = ll;
    pb[k2] = hh; pb[128 + k2] = ll; pb[256 + k2] = hh;
}

// ===========================================================================
// Distance GEMM via mma.sync bf16. 128x128 tile/CTA, 8 warps of 64x32.
// K = 768 in 12 chunks of 64 (128 B/row), double-buffered cp.async,
// SW128 smem swizzle + ldmatrix.
// ===========================================================================
#define NCHUNK (KPACK / 64)
#define BUF_BYTES 32768                    // A 16KB + B 16KB
#define SMEM_GEMM_TOTAL (2 * BUF_BYTES + 1024)

__global__ void __launch_bounds__(256) dist_gemm_mma(int n) {
    extern __shared__ char smem_raw[];
    uint32_t sraw = smem_to_u32(smem_raw);
    uint32_t sbase = (sraw + 1023) & ~1023u;   // 1KB align for swizzle
    int tid = threadIdx.x, lane = tid & 31, wid = tid >> 5;
    int bi = blockIdx.y, bj = blockIdx.x;

    const char* pa = (const char*)(g_pa + (size_t)bi * 128 * KPACK);
    const char* pb = (const char*)(g_pb + (size_t)bj * 128 * KPACK);
    const int ROWB = KPACK * 2;                // 1536 bytes per gmem row

    int seg = tid & 7, r0 = tid >> 3;

#define LOAD_CHUNK(c, buf) do { \
    uint32_t abase_ = sbase + (buf) * BUF_BYTES; \
    uint32_t bbase_ = abase_ + 16384; \
    _Pragma("unroll") \
    for (int it = 0; it < 4; ++it) { \
        int row = r0 + it * 32; \
        uint32_t off = row * 128 + seg * 16; \
        off = off ^ ((off >> 3) & 0x70); \
        CP_ASYNC16(abase_ + off, pa + (size_t)row * ROWB + (c) * 128 + seg * 16); \
        CP_ASYNC16(bbase_ + off, pb + (size_t)row * ROWB + (c) * 128 + seg * 16); \
    } \
    CP_COMMIT(); \
} while (0)

    int wr = wid >> 2, wc = wid & 3;
    int wm = wr * 64, wn = wc * 32;

    float acc[4][4][4];
#pragma unroll
    for (int mt = 0; mt < 4; ++mt)
#pragma unroll
        for (int nt = 0; nt < 4; ++nt)
#pragma unroll
            for (int e = 0; e < 4; ++e) acc[mt][nt][e] = 0.f;

    LOAD_CHUNK(0, 0);
    for (int c = 0; c < NCHUNK; ++c) {
        if (c + 1 < NCHUNK) {
            LOAD_CHUNK(c + 1, (c + 1) & 1);
            CP_WAIT(1);
        } else {
            CP_WAIT(0);
        }
        __syncthreads();
        uint32_t abase = sbase + (c & 1) * BUF_BYTES;
        uint32_t bbase = abase + 16384;
#pragma unroll
        for (int kk = 0; kk < 4; ++kk) {
            uint32_t afr[4][4], bfr[4][2];
#pragma unroll
            for (int mt = 0; mt < 4; ++mt) {
                int row = wm + mt * 16 + (lane & 15);
                uint32_t off = row * 128 + kk * 32 + (lane >> 4) * 16;
                off = off ^ ((off >> 3) & 0x70);
                LDMATRIX_X4(afr[mt], abase + off);
            }
#pragma unroll
            for (int nt = 0; nt < 4; ++nt) {
                int row = wn + nt * 8 + (lane & 7);
                uint32_t off = row * 128 + kk * 32 + ((lane >> 3) & 1) * 16;
                off = off ^ ((off >> 3) & 0x70);
                LDMATRIX_X2(bfr[nt], bbase + off);
            }
#pragma unroll
            for (int mt = 0; mt < 4; ++mt)
#pragma unroll
                for (int nt = 0; nt < 4; ++nt)
                    MMA_BF16(acc[mt][nt], afr[mt], bfr[nt]);
        }
        __syncthreads();
    }

    // epilogue: stage sq for rows and cols, then transform + store
    float* ssq = (float*)(smem_raw + (sbase - sraw));
    if (tid < 128) ssq[tid] = g_sq[bi * 128 + tid];
    else           ssq[tid] = g_sq[bj * 128 + (tid - 128)];
    __syncthreads();

    int g4 = lane >> 2, t4 = lane & 3;
#pragma unroll
    for (int mt = 0; mt < 4; ++mt) {
#pragma unroll
        for (int half = 0; half < 2; ++half) {
            int r = wm + mt * 16 + g4 + half * 8;
            int gi = bi * 128 + r;
            float sqi = ssq[r];
#pragma unroll
            for (int nt = 0; nt < 4; ++nt) {
                int col = wn + nt * 8 + 2 * t4;
                int gj = bj * 128 + col;
                float2 o;
                float d0 = sqi + ssq[128 + col] + EPS_F
                           - 2.0f * acc[mt][nt][half * 2 + 0];
                float d1 = sqi + ssq[128 + col + 1] + EPS_F
                           - 2.0f * acc[mt][nt][half * 2 + 1];
                o.x = sqrtf(fmaxf(d0, 1e-12f));
                o.y = sqrtf(fmaxf(d1, 1e-12f));
                if (gi == gj)     o.x = sqrtf(EPS_F);
                if (gi == gj + 1) o.y = sqrtf(EPS_F);
                *(float2*)(g_dist + (size_t)gi * n + gj) = o;
            }
        }
    }
#undef LOAD_CHUNK
}

// ===========================================================================
// Per-row selection + logsumexp (registers + warp pop-merge)
// ===========================================================================
#define INSERT7(t, val) do { \
    float _v = (val); \
    if (_v < t[6]) { \
        t[6] = _v; \
        _Pragma("unroll") \
        for (int _k = 6; _k > 0; --_k) { \
            float _a = t[_k-1], _b = t[_k]; \
            t[_k-1] = fminf(_a, _b); t[_k] = fmaxf(_a, _b); } \
    } } while (0)

__device__ __forceinline__ void warp_pop7(float t[7], int lane, float* out) {
#pragma unroll
    for (int r = 0; r < 7; ++r) {
        float bv = t[0]; int bl = lane;
#pragma unroll
        for (int off = 16; off; off >>= 1) {
            float ov = __shfl_down_sync(0xffffffffu, bv, off);
            int   ol = __shfl_down_sync(0xffffffffu, bl, off);
            if (ov < bv) { bv = ov; bl = ol; }
        }
        bv = __shfl_sync(0xffffffffu, bv, 0);
        bl = __shfl_sync(0xffffffffu, bl, 0);
        if (lane == bl) {
#pragma unroll
            for (int k = 0; k < 6; ++k) t[k] = t[k + 1];
            t[6] = INF_F;
        }
        if (lane == 0) out[r] = bv;
    }
}

__global__ void __launch_bounds__(256) row_kernel(int n) {
    __shared__ float s_pop[2][8][8];
    __shared__ float s_res[2][2];
    __shared__ float s_sum[2][8];

    int i = blockIdx.x, tid = threadIdx.x;
    int wid = tid >> 5, lane = tid & 31;
    const float* drow = g_dist + (size_t)i * n;
    int mycam = g_cam[i];

    float v[16];
    bool  m[16];
#pragma unroll
    for (int w = 0; w < 4; ++w) {
        int j = tid * 4 + w * 1024;
        float4 f = *(const float4*)(drow + j);
        v[w * 4 + 0] = f.x; v[w * 4 + 1] = f.y;
        v[w * 4 + 2] = f.z; v[w * 4 + 3] = f.w;
        uchar4 cc = ((const uchar4*)g_cam)[j >> 2];
        m[w * 4 + 0] = (cc.x == mycam); m[w * 4 + 1] = (cc.y == mycam);
        m[w * 4 + 2] = (cc.z == mycam); m[w * 4 + 3] = (cc.w == mycam);
    }

    float ti[7], te[7];
#pragma unroll
    for (int k = 0; k < 7; ++k) { ti[k] = INF_F; te[k] = INF_F; }
#pragma unroll
    for (int k = 0; k < 16; ++k) {
        if (m[k]) INSERT7(ti, v[k]);
        else      INSERT7(te, v[k]);
    }

    warp_pop7(ti, lane, &s_pop[0][wid][0]);
    warp_pop7(te, lane, &s_pop[1][wid][0]);
    __syncthreads();

    if (wid < 2) {   // warp 0: intra (K=4), warp 1: inter (K=6)
        float u[7];
#pragma unroll
        for (int k = 0; k < 7; ++k) u[k] = (lane < 8) ? s_pop[wid][lane][k] : INF_F;
        int K = (wid == 0) ? 4 : 6;
        float d0 = INF_F, dK = INF_F;
#pragma unroll
        for (int r = 0; r < 7; ++r) {
            float bv = u[0]; int bl = lane;
#pragma unroll
            for (int off = 16; off; off >>= 1) {
                float ov = __shfl_down_sync(0xffffffffu, bv, off);
                int   ol = __shfl_down_sync(0xffffffffu, bl, off);
                if (ov < bv) { bv = ov; bl = ol; }
            }
            bv = __shfl_sync(0xffffffffu, bv, 0);
            bl = __shfl_sync(0xffffffffu, bl, 0);
            if (lane == bl) {
#pragma unroll
                for (int k = 0; k < 6; ++k) u[k] = u[k + 1];
                u[6] = INF_F;
            }
            if (r == 0) d0 = bv;
            if (r == K) dK = bv;
        }
        if (lane == 0) { s_res[wid][0] = d0; s_res[wid][1] = dK; }
    }
    __syncthreads();

    float dKi = s_res[0][1], dKe = s_res[1][1];
    float si = 0.f, se = 0.f;
#pragma unroll
    for (int k = 0; k < 16; ++k) {
        float e = v[k];
        if (m[k]) { if (e >= dKi) si += __expf(SCALE_F * (dKi - e)); }
        else      { if (e >= dKe) se += __expf(SCALE_F * (dKe - e)); }
    }
#pragma unroll
    for (int off = 16; off; off >>= 1) {
        si += __shfl_down_sync(0xffffffffu, si, off);
        se += __shfl_down_sync(0xffffffffu, se, off);
    }
    if (lane == 0) { s_sum[0][wid] = si; s_sum[1][wid] = se; }
    __syncthreads();

    if (tid == 0) {
        float Si = 0.f, Se = 0.f;
#pragma unroll
        for (int w = 0; w < 8; ++w) { Si += s_sum[0][w]; Se += s_sum[1][w]; }
        float d0i = s_res[0][0], d0e = s_res[1][0];
        float term_i = 0.f, term_e = 0.f;
        if (isfinite(dKi))
            term_i = fmaxf(SCALE_F * (d0i - dKi) + logf(Si) + 40.0f, 0.f);
        if (isfinite(dKe))
            term_e = fmaxf(SCALE_F * (d0e - dKe) + logf(Se) + 6.0f, 0.f);
        g_partial[i] = term_i + 0.5f * term_e;
    }
}

// ===========================================================================
// Deterministic final reduction
// ===========================================================================
__global__ void final_kernel(int n, float* __restrict__ out) {
    __shared__ float sh[256];
    float s = 0.f;
    for (int j = threadIdx.x; j < n; j += 256) s += g_partial[j];
    sh[threadIdx.x] = s;
    __syncthreads();
    for (int st = 128; st; st >>= 1) {
        if (threadIdx.x < st) sh[threadIdx.x] += sh[threadIdx.x + st];
        __syncthreads();
    }
    if (threadIdx.x == 0) out[0] = sh[0] / (float)n;
}

// ===========================================================================
extern "C" void kernel_launch(void* const* d_in, const int* in_sizes, int n_in,
                              void* d_out, int out_size) {
    const float* feat = (const float*)d_in[0];
    const int*   cam  = (const int*)d_in[1];
    int n = in_sizes[1];
    int d = in_sizes[0] / n;

    static int smem_set = 0;
    if (!smem_set) {
        cudaFuncSetAttribute(dist_gemm_mma,
                             cudaFuncAttributeMaxDynamicSharedMemorySize,
                             SMEM_GEMM_TOTAL);
        smem_set = 1;
    }

    prep_cam_kernel<<<1, 256>>>(cam, n);
    sq_kernel<<<(n * 32 + 255) / 256, 256>>>(feat, n, d);
    split_pack_kernel<<<(n * d / 2 + 255) / 256, 256>>>(feat, n, d);
    dim3 grid(n / 128, n / 128);
    dist_gemm_mma<<<grid, 256, SMEM_GEMM_TOTAL>>>(n);
    row_kernel<<<n, 256>>>(n);
    final_kernel<<<1, 256>>>(n, (float*)d_out);
}

// round 4
// speedup vs baseline: 2.8684x; 1.1977x over previous
#include <cuda_runtime.h>
#include <cuda_bf16.h>
#include <math.h>
#include <stdint.h>

#define NMAX 4096
#define DMAX 256
#define KPACK 768              // [hi|hi|lo] / [hi|lo|hi]
#define SCALE_F 10.0f
#define EPS_F 1e-5f
#define INF_F __int_as_float(0x7f800000)

__device__ float g_dist[(size_t)NMAX * NMAX];
__device__ float g_sq[NMAX];
__device__ unsigned char g_cam[NMAX];
__device__ float g_partial[NMAX];
__device__ __nv_bfloat16 g_pa[(size_t)NMAX * KPACK];
__device__ __nv_bfloat16 g_pb[(size_t)NMAX * KPACK];

__device__ __forceinline__ uint32_t smem_to_u32(const void* p) {
    uint32_t a;
    asm("{ .reg .u64 t; cvta.to.shared.u64 t, %1; cvt.u32.u64 %0, t; }"
        : "=r"(a) : "l"(p));
    return a;
}

#define LDMATRIX_X4(R, addr) \
    asm volatile("ldmatrix.sync.aligned.m8n8.x4.shared.b16 {%0,%1,%2,%3}, [%4];" \
        : "=r"((R)[0]), "=r"((R)[1]), "=r"((R)[2]), "=r"((R)[3]) : "r"(addr))
#define MMA_BF16(D, A, B) \
    asm volatile("mma.sync.aligned.m16n8k16.row.col.f32.bf16.bf16.f32 " \
        "{%0,%1,%2,%3}, {%4,%5,%6,%7}, {%8,%9}, {%0,%1,%2,%3};" \
        : "+f"((D)[0]), "+f"((D)[1]), "+f"((D)[2]), "+f"((D)[3]) \
        : "r"((A)[0]), "r"((A)[1]), "r"((A)[2]), "r"((A)[3]), \
          "r"((B)[0]), "r"((B)[1]))
#define CP_ASYNC16(dst, src) \
    asm volatile("cp.async.cg.shared.global [%0], [%1], 16;" \
        :: "r"(dst), "l"(src))
#define CP_COMMIT() asm volatile("cp.async.commit_group;")
#define CP_WAIT(N)  asm volatile("cp.async.wait_group %0;" :: "n"(N))

// ===========================================================================
// camid normalization (int64-or-int32 -> uint8)
// ===========================================================================
__global__ void prep_cam_kernel(const int* __restrict__ cam_raw, int n) {
    __shared__ int s_is64;
    if (threadIdx.x == 0) {
        int is64 = 1;
        int checks = n < 128 ? n : 128;
        for (int k = 0; k < checks; ++k)
            if (cam_raw[2 * k + 1] != 0) { is64 = 0; break; }
        s_is64 = is64;
    }
    __syncthreads();
    int is64 = s_is64;
    for (int j = threadIdx.x; j < n; j += blockDim.x)
        g_cam[j] = (unsigned char)(is64 ? cam_raw[2 * j] : cam_raw[j]);
}

// ===========================================================================
// Row squared norms
// ===========================================================================
__global__ void sq_kernel(const float* __restrict__ feat, int n, int d) {
    int warp = (blockIdx.x * blockDim.x + threadIdx.x) >> 5;
    int lane = threadIdx.x & 31;
    if (warp >= n) return;
    const float* row = feat + (size_t)warp * d;
    float s = 0.f;
    for (int k = lane * 4; k < d; k += 32 * 4) {
        float4 v = *(const float4*)(row + k);
        s += v.x * v.x + v.y * v.y + v.z * v.z + v.w * v.w;
    }
#pragma unroll
    for (int off = 16; off; off >>= 1) s += __shfl_down_sync(0xffffffffu, s, off);
    if (lane == 0) g_sq[warp] = s;
}

// ===========================================================================
// Split f32 -> bf16 hi+lo, pack A'=[hi|hi|lo], B'=[hi|lo|hi] (K=768)
// ===========================================================================
__global__ void split_pack_kernel(const float* __restrict__ f, int n, int d) {
    int idx = blockIdx.x * blockDim.x + threadIdx.x;   // one per 2 elems
    int half_d = d >> 1;                               // 128
    if (idx >= n * half_d) return;
    int i  = idx / half_d;
    int k2 = idx - i * half_d;
    float2 x = ((const float2*)f)[idx];
    __nv_bfloat16 h0 = __float2bfloat16_rn(x.x);
    __nv_bfloat16 h1 = __float2bfloat16_rn(x.y);
    __nv_bfloat16 l0 = __float2bfloat16_rn(x.x - __bfloat162float(h0));
    __nv_bfloat16 l1 = __float2bfloat16_rn(x.y - __bfloat162float(h1));
    __nv_bfloat162 hh(h0, h1), ll(l0, l1);
    __nv_bfloat162* pa = (__nv_bfloat162*)(g_pa + (size_t)i * KPACK);
    __nv_bfloat162* pb = (__nv_bfloat162*)(g_pb + (size_t)i * KPACK);
    pa[k2] = hh; pa[128 + k2] = hh; pa[256 + k2] = ll;
    pb[k2] = hh; pb[128 + k2] = ll; pb[256 + k2] = hh;
}

// ===========================================================================
// Distance GEMM via mma.sync bf16, UPPER-TRIANGLE blocks only (exact
// symmetry of hi.hi + hi.lo + lo.hi), mirror tile written via smem staging.
// 128x128 tile/CTA, 8 warps of 64x32. K=768, 12 chunks of 64,
// double-buffered cp.async, SW128 swizzle + ldmatrix.
// ===========================================================================
#define NCHUNK (KPACK / 64)
#define BUF_BYTES 32768                    // A 16KB + B 16KB
#define TLDA 129                           // f32 tile staging leading dim
#define SMEM_GEMM_TOTAL (1024 + 128 * TLDA * 4)   // 67072 >= 1024+65536 too

__global__ void __launch_bounds__(256) dist_gemm_mma(int n) {
    extern __shared__ char smem_raw[];
    uint32_t sraw = smem_to_u32(smem_raw);
    uint32_t sbase = (sraw + 1023) & ~1023u;   // 1KB align for swizzle
    int tid = threadIdx.x, lane = tid & 31, wid = tid >> 5;

    // triangular decode: block t -> (bi, bj), bi <= bj
    int NB = n >> 7;
    int t = blockIdx.x;
    int bi = (int)((2.0f * NB + 1.0f -
                    sqrtf((2.0f * NB + 1.0f) * (2.0f * NB + 1.0f) - 8.0f * t)) * 0.5f);
    if (bi < 0) bi = 0;
    if (bi > NB - 1) bi = NB - 1;
#define TRI_START(r) ((r) * NB - ((r) * ((r) - 1)) / 2)
    while (bi + 1 < NB && TRI_START(bi + 1) <= t) ++bi;
    while (bi > 0 && TRI_START(bi) > t) --bi;
    int bj = bi + (t - TRI_START(bi));
#undef TRI_START

    const char* pa = (const char*)(g_pa + (size_t)bi * 128 * KPACK);
    const char* pb = (const char*)(g_pb + (size_t)bj * 128 * KPACK);
    const int ROWB = KPACK * 2;                // 1536 bytes per gmem row

    int seg = tid & 7, r0 = tid >> 3;

#define LOAD_CHUNK(c, buf) do { \
    uint32_t abase_ = sbase + (buf) * BUF_BYTES; \
    uint32_t bbase_ = abase_ + 16384; \
    _Pragma("unroll") \
    for (int it = 0; it < 4; ++it) { \
        int row = r0 + it * 32; \
        uint32_t off = row * 128 + seg * 16; \
        off = off ^ ((off >> 3) & 0x70); \
        CP_ASYNC16(abase_ + off, pa + (size_t)row * ROWB + (c) * 128 + seg * 16); \
        CP_ASYNC16(bbase_ + off, pb + (size_t)row * ROWB + (c) * 128 + seg * 16); \
    } \
    CP_COMMIT(); \
} while (0)

    int wr = wid >> 2, wc = wid & 3;
    int wm = wr * 64, wn = wc * 32;

    float acc[4][4][4];
#pragma unroll
    for (int mt = 0; mt < 4; ++mt)
#pragma unroll
        for (int nt = 0; nt < 4; ++nt)
#pragma unroll
            for (int e = 0; e < 4; ++e) acc[mt][nt][e] = 0.f;

    LOAD_CHUNK(0, 0);
    for (int c = 0; c < NCHUNK; ++c) {
        if (c + 1 < NCHUNK) {
            LOAD_CHUNK(c + 1, (c + 1) & 1);
            CP_WAIT(1);
        } else {
            CP_WAIT(0);
        }
        __syncthreads();
        uint32_t abase = sbase + (c & 1) * BUF_BYTES;
        uint32_t bbase = abase + 16384;
#pragma unroll
        for (int kk = 0; kk < 4; ++kk) {
            uint32_t afr[4][4], bfr[4][2];
#pragma unroll
            for (int mt = 0; mt < 4; ++mt) {
                int row = wm + mt * 16 + (lane & 15);
                uint32_t off = row * 128 + kk * 32 + (lane >> 4) * 16;
                off = off ^ ((off >> 3) & 0x70);
                LDMATRIX_X4(afr[mt], abase + off);
            }
#pragma unroll
            for (int np = 0; np < 2; ++np) {   // x4: 2 n-tiles per load
                int row = wn + np * 16 + ((lane >> 4) << 3) + (lane & 7);
                uint32_t off = row * 128 + kk * 32 + (((lane >> 3) & 1) << 4);
                off = off ^ ((off >> 3) & 0x70);
                uint32_t q[4];
                LDMATRIX_X4(q, bbase + off);
                bfr[np * 2 + 0][0] = q[0]; bfr[np * 2 + 0][1] = q[1];
                bfr[np * 2 + 1][0] = q[2]; bfr[np * 2 + 1][1] = q[3];
            }
#pragma unroll
            for (int mt = 0; mt < 4; ++mt)
#pragma unroll
                for (int nt = 0; nt < 4; ++nt)
                    MMA_BF16(acc[mt][nt], afr[mt], bfr[nt]);
        }
        __syncthreads();
    }

    // ---- epilogue ----
    __shared__ float ssq[256];
    float* s_tile = (float*)(smem_raw + (sbase - sraw));
    if (tid < 128) ssq[tid] = g_sq[bi * 128 + tid];
    else           ssq[tid] = g_sq[bj * 128 + (tid - 128)];
    __syncthreads();

    int g4 = lane >> 2, t4 = lane & 3;
#pragma unroll
    for (int mt = 0; mt < 4; ++mt) {
#pragma unroll
        for (int half = 0; half < 2; ++half) {
            int r = wm + mt * 16 + g4 + half * 8;
            int gi = bi * 128 + r;
            float sqi = ssq[r];
#pragma unroll
            for (int nt = 0; nt < 4; ++nt) {
                int col = wn + nt * 8 + 2 * t4;
                int gj = bj * 128 + col;
                float2 o;
                float d0 = sqi + ssq[128 + col] + EPS_F
                           - 2.0f * acc[mt][nt][half * 2 + 0];
                float d1 = sqi + ssq[128 + col + 1] + EPS_F
                           - 2.0f * acc[mt][nt][half * 2 + 1];
                o.x = sqrtf(fmaxf(d0, 1e-12f));
                o.y = sqrtf(fmaxf(d1, 1e-12f));
                if (gi == gj)     o.x = sqrtf(EPS_F);
                if (gi == gj + 1) o.y = sqrtf(EPS_F);
                *(float2*)(g_dist + (size_t)gi * n + gj) = o;
                s_tile[r * TLDA + col]     = o.x;
                s_tile[r * TLDA + col + 1] = o.y;
            }
        }
    }

    // mirror block (bj, bi): coalesced store from staged tile
    if (bi != bj) {
        __syncthreads();
#pragma unroll
        for (int it = 0; it < 16; ++it) {
            int c = it * 8 + wid;                        // tile column
            float* orow = g_dist + (size_t)(bj * 128 + c) * n + bi * 128;
#pragma unroll
            for (int q = 0; q < 4; ++q) {
                int r = lane + q * 32;
                orow[r] = s_tile[r * TLDA + c];          // bank-conflict-free
            }
        }
    }
#undef LOAD_CHUNK
}

// ===========================================================================
// Per-row selection + logsumexp (registers + warp pop-merge)
// ===========================================================================
#define INSERT7(t, val) do { \
    float _v = (val); \
    if (_v < t[6]) { \
        t[6] = _v; \
        _Pragma("unroll") \
        for (int _k = 6; _k > 0; --_k) { \
            float _a = t[_k-1], _b = t[_k]; \
            t[_k-1] = fminf(_a, _b); t[_k] = fmaxf(_a, _b); } \
    } } while (0)

__device__ __forceinline__ void warp_pop7(float t[7], int lane, float* out) {
#pragma unroll
    for (int r = 0; r < 7; ++r) {
        float bv = t[0]; int bl = lane;
#pragma unroll
        for (int off = 16; off; off >>= 1) {
            float ov = __shfl_down_sync(0xffffffffu, bv, off);
            int   ol = __shfl_down_sync(0xffffffffu, bl, off);
            if (ov < bv) { bv = ov; bl = ol; }
        }
        bv = __shfl_sync(0xffffffffu, bv, 0);
        bl = __shfl_sync(0xffffffffu, bl, 0);
        if (lane == bl) {
#pragma unroll
            for (int k = 0; k < 6; ++k) t[k] = t[k + 1];
            t[6] = INF_F;
        }
        if (lane == 0) out[r] = bv;
    }
}

__global__ void __launch_bounds__(256) row_kernel(int n) {
    __shared__ float s_pop[2][8][8];
    __shared__ float s_res[2][2];
    __shared__ float s_sum[2][8];

    int i = blockIdx.x, tid = threadIdx.x;
    int wid = tid >> 5, lane = tid & 31;
    const float* drow = g_dist + (size_t)i * n;
    int mycam = g_cam[i];

    float v[16];
    bool  m[16];
#pragma unroll
    for (int w = 0; w < 4; ++w) {
        int j = tid * 4 + w * 1024;
        float4 f = *(const float4*)(drow + j);
        v[w * 4 + 0] = f.x; v[w * 4 + 1] = f.y;
        v[w * 4 + 2] = f.z; v[w * 4 + 3] = f.w;
        uchar4 cc = ((const uchar4*)g_cam)[j >> 2];
        m[w * 4 + 0] = (cc.x == mycam); m[w * 4 + 1] = (cc.y == mycam);
        m[w * 4 + 2] = (cc.z == mycam); m[w * 4 + 3] = (cc.w == mycam);
    }

    float ti[7], te[7];
#pragma unroll
    for (int k = 0; k < 7; ++k) { ti[k] = INF_F; te[k] = INF_F; }
#pragma unroll
    for (int k = 0; k < 16; ++k) {
        if (m[k]) INSERT7(ti, v[k]);
        else      INSERT7(te, v[k]);
    }

    warp_pop7(ti, lane, &s_pop[0][wid][0]);
    warp_pop7(te, lane, &s_pop[1][wid][0]);
    __syncthreads();

    if (wid < 2) {   // warp 0: intra (K=4), warp 1: inter (K=6)
        float u[7];
#pragma unroll
        for (int k = 0; k < 7; ++k) u[k] = (lane < 8) ? s_pop[wid][lane][k] : INF_F;
        int K = (wid == 0) ? 4 : 6;
        float d0 = INF_F, dK = INF_F;
#pragma unroll
        for (int r = 0; r < 7; ++r) {
            float bv = u[0]; int bl = lane;
#pragma unroll
            for (int off = 16; off; off >>= 1) {
                float ov = __shfl_down_sync(0xffffffffu, bv, off);
                int   ol = __shfl_down_sync(0xffffffffu, bl, off);
                if (ov < bv) { bv = ov; bl = ol; }
            }
            bv = __shfl_sync(0xffffffffu, bv, 0);
            bl = __shfl_sync(0xffffffffu, bl, 0);
            if (lane == bl) {
#pragma unroll
                for (int k = 0; k < 6; ++k) u[k] = u[k + 1];
                u[6] = INF_F;
            }
            if (r == 0) d0 = bv;
            if (r == K) dK = bv;
        }
        if (lane == 0) { s_res[wid][0] = d0; s_res[wid][1] = dK; }
    }
    __syncthreads();

    float dKi = s_res[0][1], dKe = s_res[1][1];
    float si = 0.f, se = 0.f;
#pragma unroll
    for (int k = 0; k < 16; ++k) {
        float e = v[k];
        if (m[k]) { if (e >= dKi) si += __expf(SCALE_F * (dKi - e)); }
        else      { if (e >= dKe) se += __expf(SCALE_F * (dKe - e)); }
    }
#pragma unroll
    for (int off = 16; off; off >>= 1) {
        si += __shfl_down_sync(0xffffffffu, si, off);
        se += __shfl_down_sync(0xffffffffu, se, off);
    }
    if (lane == 0) { s_sum[0][wid] = si; s_sum[1][wid] = se; }
    __syncthreads();

    if (tid == 0) {
        float Si = 0.f, Se = 0.f;
#pragma unroll
        for (int w = 0; w < 8; ++w) { Si += s_sum[0][w]; Se += s_sum[1][w]; }
        float d0i = s_res[0][0], d0e = s_res[1][0];
        float term_i = 0.f, term_e = 0.f;
        if (isfinite(dKi))
            term_i = fmaxf(SCALE_F * (d0i - dKi) + logf(Si) + 40.0f, 0.f);
        if (isfinite(dKe))
            term_e = fmaxf(SCALE_F * (d0e - dKe) + logf(Se) + 6.0f, 0.f);
        g_partial[i] = term_i + 0.5f * term_e;
    }
}

// ===========================================================================
// Deterministic final reduction
// ===========================================================================
__global__ void final_kernel(int n, float* __restrict__ out) {
    __shared__ float sh[256];
    float s = 0.f;
    for (int j = threadIdx.x; j < n; j += 256) s += g_partial[j];
    sh[threadIdx.x] = s;
    __syncthreads();
    for (int st = 128; st; st >>= 1) {
        if (threadIdx.x < st) sh[threadIdx.x] += sh[threadIdx.x + st];
        __syncthreads();
    }
    if (threadIdx.x == 0) out[0] = sh[0] / (float)n;
}

// ===========================================================================
extern "C" void kernel_launch(void* const* d_in, const int* in_sizes, int n_in,
                              void* d_out, int out_size) {
    const float* feat = (const float*)d_in[0];
    const int*   cam  = (const int*)d_in[1];
    int n = in_sizes[1];
    int d = in_sizes[0] / n;
    int NB = n / 128;

    static int smem_set = 0;
    if (!smem_set) {
        cudaFuncSetAttribute(dist_gemm_mma,
                             cudaFuncAttributeMaxDynamicSharedMemorySize,
                             SMEM_GEMM_TOTAL);
        smem_set = 1;
    }

    prep_cam_kernel<<<1, 256>>>(cam, n);
    sq_kernel<<<(n * 32 + 255) / 256, 256>>>(feat, n, d);
    split_pack_kernel<<<(n * d / 2 + 255) / 256, 256>>>(feat, n, d);
    dist_gemm_mma<<<NB * (NB + 1) / 2, 256, SMEM_GEMM_TOTAL>>>(n);
    row_kernel<<<n, 256>>>(n);
    final_kernel<<<1, 256>>>(n, (float*)d_out);
}

// round 5
// speedup vs baseline: 2.9251x; 1.0198x over previous
#include <cuda_runtime.h>
#include <cuda_bf16.h>
#include <math.h>
#include <stdint.h>

#define NMAX 4096
#define DMAX 256
#define KPACK 768              // [hi|hi|lo] / [hi|lo|hi]
#define SCALE_F 10.0f
#define EPS_F 1e-5f
#define INF_F __int_as_float(0x7f800000)

__device__ float g_dist[(size_t)NMAX * NMAX];
__device__ float g_sq[NMAX];
__device__ unsigned char g_cam[NMAX];
__device__ float g_partial[NMAX];
__device__ __nv_bfloat16 g_pa[(size_t)NMAX * KPACK];
__device__ __nv_bfloat16 g_pb[(size_t)NMAX * KPACK];

__device__ __forceinline__ uint32_t smem_to_u32(const void* p) {
    uint32_t a;
    asm("{ .reg .u64 t; cvta.to.shared.u64 t, %1; cvt.u32.u64 %0, t; }"
        : "=r"(a) : "l"(p));
    return a;
}

#define LDMATRIX_X4(R, addr) \
    asm volatile("ldmatrix.sync.aligned.m8n8.x4.shared.b16 {%0,%1,%2,%3}, [%4];" \
        : "=r"((R)[0]), "=r"((R)[1]), "=r"((R)[2]), "=r"((R)[3]) : "r"(addr))
#define MMA_BF16(D, A, B) \
    asm volatile("mma.sync.aligned.m16n8k16.row.col.f32.bf16.bf16.f32 " \
        "{%0,%1,%2,%3}, {%4,%5,%6,%7}, {%8,%9}, {%0,%1,%2,%3};" \
        : "+f"((D)[0]), "+f"((D)[1]), "+f"((D)[2]), "+f"((D)[3]) \
        : "r"((A)[0]), "r"((A)[1]), "r"((A)[2]), "r"((A)[3]), \
          "r"((B)[0]), "r"((B)[1]))
#define CP_ASYNC16(dst, src) \
    asm volatile("cp.async.cg.shared.global [%0], [%1], 16;" \
        :: "r"(dst), "l"(src))
#define CP_COMMIT() asm volatile("cp.async.commit_group;")
#define CP_WAIT(N)  asm volatile("cp.async.wait_group %0;" :: "n"(N))

// ===========================================================================
// Fused prep: camid normalize + row sq norms + split/pack (independent jobs,
// dispatched by blockIdx range to cut launch count).
// ===========================================================================
__global__ void prep_fused_kernel(const float* __restrict__ f,
                                  const int* __restrict__ cam_raw,
                                  int n, int d,
                                  int splitBlocks, int sqBlocks) {
    int b = blockIdx.x;
    if (b < splitBlocks) {
        // ---- split f32 -> bf16 hi+lo, pack A'=[hi|hi|lo], B'=[hi|lo|hi]
        int idx = b * blockDim.x + threadIdx.x;     // one per 2 elems
        int half_d = d >> 1;                        // 128
        if (idx >= n * half_d) return;
        int i  = idx / half_d;
        int k2 = idx - i * half_d;
        float2 x = ((const float2*)f)[idx];
        __nv_bfloat16 h0 = __float2bfloat16_rn(x.x);
        __nv_bfloat16 h1 = __float2bfloat16_rn(x.y);
        __nv_bfloat16 l0 = __float2bfloat16_rn(x.x - __bfloat162float(h0));
        __nv_bfloat16 l1 = __float2bfloat16_rn(x.y - __bfloat162float(h1));
        __nv_bfloat162 hh(h0, h1), ll(l0, l1);
        __nv_bfloat162* pa = (__nv_bfloat162*)(g_pa + (size_t)i * KPACK);
        __nv_bfloat162* pb = (__nv_bfloat162*)(g_pb + (size_t)i * KPACK);
        pa[k2] = hh; pa[128 + k2] = hh; pa[256 + k2] = ll;
        pb[k2] = hh; pb[128 + k2] = ll; pb[256 + k2] = hh;
    } else if (b < splitBlocks + sqBlocks) {
        // ---- row squared norms: one warp per row
        int warp = ((b - splitBlocks) * blockDim.x + threadIdx.x) >> 5;
        int lane = threadIdx.x & 31;
        if (warp >= n) return;
        const float* row = f + (size_t)warp * d;
        float s = 0.f;
        for (int k = lane * 4; k < d; k += 32 * 4) {
            float4 v = *(const float4*)(row + k);
            s += v.x * v.x + v.y * v.y + v.z * v.z + v.w * v.w;
        }
#pragma unroll
        for (int off = 16; off; off >>= 1) s += __shfl_down_sync(0xffffffffu, s, off);
        if (lane == 0) g_sq[warp] = s;
    } else {
        // ---- camid normalization (int64-or-int32 -> uint8)
        __shared__ int s_is64;
        if (threadIdx.x == 0) {
            int is64 = 1;
            int checks = n < 128 ? n : 128;
            for (int k = 0; k < checks; ++k)
                if (cam_raw[2 * k + 1] != 0) { is64 = 0; break; }
            s_is64 = is64;
        }
        __syncthreads();
        int is64 = s_is64;
        for (int j = threadIdx.x; j < n; j += blockDim.x)
            g_cam[j] = (unsigned char)(is64 ? cam_raw[2 * j] : cam_raw[j]);
    }
}

// ===========================================================================
// Distance GEMM via mma.sync bf16, UPPER-TRIANGLE blocks only (exact
// symmetry of hi.hi + hi.lo + lo.hi), mirror tile written via smem staging.
// 128x128 tile/CTA, 8 warps of 64x32. K=768, 12 chunks of 64,
// 3-stage cp.async pipeline, SW128 swizzle + ldmatrix.
// ===========================================================================
#define NCHUNK (KPACK / 64)
#define BUF_BYTES 32768                    // A 16KB + B 16KB
#define TLDA 129                           // f32 tile staging leading dim
#define SMEM_GEMM_TOTAL (1024 + 3 * BUF_BYTES)   // 99328; staging fits inside

__global__ void __launch_bounds__(256) dist_gemm_mma(int n) {
    extern __shared__ char smem_raw[];
    uint32_t sraw = smem_to_u32(smem_raw);
    uint32_t sbase = (sraw + 1023) & ~1023u;   // 1KB align for swizzle
    int tid = threadIdx.x, lane = tid & 31, wid = tid >> 5;

    // triangular decode: block t -> (bi, bj), bi <= bj
    int NB = n >> 7;
    int t = blockIdx.x;
    int bi = (int)((2.0f * NB + 1.0f -
                    sqrtf((2.0f * NB + 1.0f) * (2.0f * NB + 1.0f) - 8.0f * t)) * 0.5f);
    if (bi < 0) bi = 0;
    if (bi > NB - 1) bi = NB - 1;
#define TRI_START(r) ((r) * NB - ((r) * ((r) - 1)) / 2)
    while (bi + 1 < NB && TRI_START(bi + 1) <= t) ++bi;
    while (bi > 0 && TRI_START(bi) > t) --bi;
    int bj = bi + (t - TRI_START(bi));
#undef TRI_START

    const char* pa = (const char*)(g_pa + (size_t)bi * 128 * KPACK);
    const char* pb = (const char*)(g_pb + (size_t)bj * 128 * KPACK);
    const int ROWB = KPACK * 2;                // 1536 bytes per gmem row

    int seg = tid & 7, r0 = tid >> 3;

#define LOAD_CHUNK(c, buf) do { \
    uint32_t abase_ = sbase + (buf) * BUF_BYTES; \
    uint32_t bbase_ = abase_ + 16384; \
    _Pragma("unroll") \
    for (int it = 0; it < 4; ++it) { \
        int row = r0 + it * 32; \
        uint32_t off = row * 128 + seg * 16; \
        off = off ^ ((off >> 3) & 0x70); \
        CP_ASYNC16(abase_ + off, pa + (size_t)row * ROWB + (c) * 128 + seg * 16); \
        CP_ASYNC16(bbase_ + off, pb + (size_t)row * ROWB + (c) * 128 + seg * 16); \
    } \
    CP_COMMIT(); \
} while (0)

    int wr = wid >> 2, wc = wid & 3;
    int wm = wr * 64, wn = wc * 32;

    float acc[4][4][4];
#pragma unroll
    for (int mt = 0; mt < 4; ++mt)
#pragma unroll
        for (int nt = 0; nt < 4; ++nt)
#pragma unroll
            for (int e = 0; e < 4; ++e) acc[mt][nt][e] = 0.f;

    LOAD_CHUNK(0, 0);
    LOAD_CHUNK(1, 1);
    for (int c = 0; c < NCHUNK; ++c) {
        if (c == NCHUNK - 1) CP_WAIT(0);
        else                 CP_WAIT(1);       // chunk c complete
        __syncthreads();                       // data visible; prev compute done
        if (c + 2 < NCHUNK) LOAD_CHUNK(c + 2, (c + 2) % 3);

        uint32_t abase = sbase + (c % 3) * BUF_BYTES;
        uint32_t bbase = abase + 16384;
#pragma unroll
        for (int kk = 0; kk < 4; ++kk) {
            uint32_t afr[4][4], bfr[4][2];
#pragma unroll
            for (int mt = 0; mt < 4; ++mt) {
                int row = wm + mt * 16 + (lane & 15);
                uint32_t off = row * 128 + kk * 32 + (lane >> 4) * 16;
                off = off ^ ((off >> 3) & 0x70);
                LDMATRIX_X4(afr[mt], abase + off);
            }
#pragma unroll
            for (int np = 0; np < 2; ++np) {   // x4: 2 n-tiles per load
                int row = wn + np * 16 + ((lane >> 4) << 3) + (lane & 7);
                uint32_t off = row * 128 + kk * 32 + (((lane >> 3) & 1) << 4);
                off = off ^ ((off >> 3) & 0x70);
                uint32_t q[4];
                LDMATRIX_X4(q, bbase + off);
                bfr[np * 2 + 0][0] = q[0]; bfr[np * 2 + 0][1] = q[1];
                bfr[np * 2 + 1][0] = q[2]; bfr[np * 2 + 1][1] = q[3];
            }
#pragma unroll
            for (int mt = 0; mt < 4; ++mt)
#pragma unroll
                for (int nt = 0; nt < 4; ++nt)
                    MMA_BF16(acc[mt][nt], afr[mt], bfr[nt]);
        }
    }

    // ---- epilogue ----
    __shared__ float ssq[256];
    float* s_tile = (float*)(smem_raw + (sbase - sraw));
    if (tid < 128) ssq[tid] = g_sq[bi * 128 + tid];
    else           ssq[tid] = g_sq[bj * 128 + (tid - 128)];
    __syncthreads();   // all warps done with mainloop smem before s_tile reuse

    int g4 = lane >> 2, t4 = lane & 3;
#pragma unroll
    for (int mt = 0; mt < 4; ++mt) {
#pragma unroll
        for (int half = 0; half < 2; ++half) {
            int r = wm + mt * 16 + g4 + half * 8;
            int gi = bi * 128 + r;
            float sqi = ssq[r];
#pragma unroll
            for (int nt = 0; nt < 4; ++nt) {
                int col = wn + nt * 8 + 2 * t4;
                int gj = bj * 128 + col;
                float2 o;
                float d0 = sqi + ssq[128 + col] + EPS_F
                           - 2.0f * acc[mt][nt][half * 2 + 0];
                float d1 = sqi + ssq[128 + col + 1] + EPS_F
                           - 2.0f * acc[mt][nt][half * 2 + 1];
                o.x = sqrtf(fmaxf(d0, 1e-12f));
                o.y = sqrtf(fmaxf(d1, 1e-12f));
                if (gi == gj)     o.x = sqrtf(EPS_F);
                if (gi == gj + 1) o.y = sqrtf(EPS_F);
                *(float2*)(g_dist + (size_t)gi * n + gj) = o;
                s_tile[r * TLDA + col]     = o.x;
                s_tile[r * TLDA + col + 1] = o.y;
            }
        }
    }

    // mirror block (bj, bi): coalesced store from staged tile
    if (bi != bj) {
        __syncthreads();
#pragma unroll
        for (int it = 0; it < 16; ++it) {
            int c = it * 8 + wid;                        // tile column
            float* orow = g_dist + (size_t)(bj * 128 + c) * n + bi * 128;
#pragma unroll
            for (int q = 0; q < 4; ++q) {
                int r = lane + q * 32;
                orow[r] = s_tile[r * TLDA + c];          // bank-conflict-free
            }
        }
    }
#undef LOAD_CHUNK
}

// ===========================================================================
// Per-row selection + logsumexp (registers + warp pop-merge)
// ===========================================================================
#define INSERT7(t, val) do { \
    float _v = (val); \
    if (_v < t[6]) { \
        t[6] = _v; \
        _Pragma("unroll") \
        for (int _k = 6; _k > 0; --_k) { \
            float _a = t[_k-1], _b = t[_k]; \
            t[_k-1] = fminf(_a, _b); t[_k] = fmaxf(_a, _b); } \
    } } while (0)

__device__ __forceinline__ void warp_pop7(float t[7], int lane, float* out) {
#pragma unroll
    for (int r = 0; r < 7; ++r) {
        float bv = t[0]; int bl = lane;
#pragma unroll
        for (int off = 16; off; off >>= 1) {
            float ov = __shfl_down_sync(0xffffffffu, bv, off);
            int   ol = __shfl_down_sync(0xffffffffu, bl, off);
            if (ov < bv) { bv = ov; bl = ol; }
        }
        bv = __shfl_sync(0xffffffffu, bv, 0);
        bl = __shfl_sync(0xffffffffu, bl, 0);
        if (lane == bl) {
#pragma unroll
            for (int k = 0; k < 6; ++k) t[k] = t[k + 1];
            t[6] = INF_F;
        }
        if (lane == 0) out[r] = bv;
    }
}

__global__ void __launch_bounds__(256) row_kernel(int n) {
    __shared__ float s_pop[2][8][8];
    __shared__ float s_res[2][2];
    __shared__ float s_sum[2][8];

    int i = blockIdx.x, tid = threadIdx.x;
    int wid = tid >> 5, lane = tid & 31;
    const float* drow = g_dist + (size_t)i * n;
    int mycam = g_cam[i];

    float v[16];
    bool  m[16];
#pragma unroll
    for (int w = 0; w < 4; ++w) {
        int j = tid * 4 + w * 1024;
        float4 f = *(const float4*)(drow + j);
        v[w * 4 + 0] = f.x; v[w * 4 + 1] = f.y;
        v[w * 4 + 2] = f.z; v[w * 4 + 3] = f.w;
        uchar4 cc = ((const uchar4*)g_cam)[j >> 2];
        m[w * 4 + 0] = (cc.x == mycam); m[w * 4 + 1] = (cc.y == mycam);
        m[w * 4 + 2] = (cc.z == mycam); m[w * 4 + 3] = (cc.w == mycam);
    }

    float ti[7], te[7];
#pragma unroll
    for (int k = 0; k < 7; ++k) { ti[k] = INF_F; te[k] = INF_F; }
#pragma unroll
    for (int k = 0; k < 16; ++k) {
        if (m[k]) INSERT7(ti, v[k]);
        else      INSERT7(te, v[k]);
    }

    warp_pop7(ti, lane, &s_pop[0][wid][0]);
    warp_pop7(te, lane, &s_pop[1][wid][0]);
    __syncthreads();

    if (wid < 2) {   // warp 0: intra (K=4), warp 1: inter (K=6)
        float u[7];
#pragma unroll
        for (int k = 0; k < 7; ++k) u[k] = (lane < 8) ? s_pop[wid][lane][k] : INF_F;
        int K = (wid == 0) ? 4 : 6;
        float d0 = INF_F, dK = INF_F;
#pragma unroll
        for (int r = 0; r < 7; ++r) {
            float bv = u[0]; int bl = lane;
#pragma unroll
            for (int off = 16; off; off >>= 1) {
                float ov = __shfl_down_sync(0xffffffffu, bv, off);
                int   ol = __shfl_down_sync(0xffffffffu, bl, off);
                if (ov < bv) { bv = ov; bl = ol; }
            }
            bv = __shfl_sync(0xffffffffu, bv, 0);
            bl = __shfl_sync(0xffffffffu, bl, 0);
            if (lane == bl) {
#pragma unroll
                for (int k = 0; k < 6; ++k) u[k] = u[k + 1];
                u[6] = INF_F;
            }
            if (r == 0) d0 = bv;
            if (r == K) dK = bv;
        }
        if (lane == 0) { s_res[wid][0] = d0; s_res[wid][1] = dK; }
    }
    __syncthreads();

    float dKi = s_res[0][1], dKe = s_res[1][1];
    float si = 0.f, se = 0.f;
#pragma unroll
    for (int k = 0; k < 16; ++k) {
        float e = v[k];
        if (m[k]) { if (e >= dKi) si += __expf(SCALE_F * (dKi - e)); }
        else      { if (e >= dKe) se += __expf(SCALE_F * (dKe - e)); }
    }
#pragma unroll
    for (int off = 16; off; off >>= 1) {
        si += __shfl_down_sync(0xffffffffu, si, off);
        se += __shfl_down_sync(0xffffffffu, se, off);
    }
    if (lane == 0) { s_sum[0][wid] = si; s_sum[1][wid] = se; }
    __syncthreads();

    if (tid == 0) {
        float Si = 0.f, Se = 0.f;
#pragma unroll
        for (int w = 0; w < 8; ++w) { Si += s_sum[0][w]; Se += s_sum[1][w]; }
        float d0i = s_res[0][0], d0e = s_res[1][0];
        float term_i = 0.f, term_e = 0.f;
        if (isfinite(dKi))
            term_i = fmaxf(SCALE_F * (d0i - dKi) + logf(Si) + 40.0f, 0.f);
        if (isfinite(dKe))
            term_e = fmaxf(SCALE_F * (d0e - dKe) + logf(Se) + 6.0f, 0.f);
        g_partial[i] = term_i + 0.5f * term_e;
    }
}

// ===========================================================================
// Deterministic final reduction
// ===========================================================================
__global__ void final_kernel(int n, float* __restrict__ out) {
    __shared__ float sh[256];
    float s = 0.f;
    for (int j = threadIdx.x; j < n; j += 256) s += g_partial[j];
    sh[threadIdx.x] = s;
    __syncthreads();
    for (int st = 128; st; st >>= 1) {
        if (threadIdx.x < st) sh[threadIdx.x] += sh[threadIdx.x + st];
        __syncthreads();
    }
    if (threadIdx.x == 0) out[0] = sh[0] / (float)n;
}

// ===========================================================================
extern "C" void kernel_launch(void* const* d_in, const int* in_sizes, int n_in,
                              void* d_out, int out_size) {
    const float* feat = (const float*)d_in[0];
    const int*   cam  = (const int*)d_in[1];
    int n = in_sizes[1];
    int d = in_sizes[0] / n;
    int NB = n / 128;

    static int smem_set = 0;
    if (!smem_set) {
        cudaFuncSetAttribute(dist_gemm_mma,
                             cudaFuncAttributeMaxDynamicSharedMemorySize,
                             SMEM_GEMM_TOTAL);
        smem_set = 1;
    }

    int splitBlocks = (n * d / 2 + 255) / 256;   // 2048
    int sqBlocks    = (n * 32 + 255) / 256;      // 512
    prep_fused_kernel<<<splitBlocks + sqBlocks + 1, 256>>>(
        feat, cam, n, d, splitBlocks, sqBlocks);
    dist_gemm_mma<<<NB * (NB + 1) / 2, 256, SMEM_GEMM_TOTAL>>>(n);
    row_kernel<<<n, 256>>>(n);
    final_kernel<<<1, 256>>>(n, (float*)d_out);
}

// round 6
// speedup vs baseline: 2.9589x; 1.0116x over previous
#include <cuda_runtime.h>
#include <cuda_bf16.h>
#include <cuda_fp16.h>
#include <math.h>
#include <stdint.h>

#define NMAX 4096
#define DMAX 256
#define KPACK 768              // [hi|hi|lo] / [hi|lo|hi]
#define SCALE_F 10.0f
#define EPS_F 1e-5f
#define INF_F __int_as_float(0x7f800000)
#define L2E10 14.4269504089f   // 10 * log2(e)

__device__ float g_dist[(size_t)NMAX * NMAX];
__device__ float g_sq[NMAX];
__device__ unsigned char g_cam[NMAX];
__device__ float g_partial[NMAX];
__device__ int g_ctr = 0;
__device__ __nv_bfloat16 g_pa[(size_t)NMAX * KPACK];
__device__ __nv_bfloat16 g_pb[(size_t)NMAX * KPACK];

__device__ __forceinline__ uint32_t smem_to_u32(const void* p) {
    uint32_t a;
    asm("{ .reg .u64 t; cvta.to.shared.u64 t, %1; cvt.u32.u64 %0, t; }"
        : "=r"(a) : "l"(p));
    return a;
}

#define LDMATRIX_X4(R, addr) \
    asm volatile("ldmatrix.sync.aligned.m8n8.x4.shared.b16 {%0,%1,%2,%3}, [%4];" \
        : "=r"((R)[0]), "=r"((R)[1]), "=r"((R)[2]), "=r"((R)[3]) : "r"(addr))
#define MMA_BF16(D, A, B) \
    asm volatile("mma.sync.aligned.m16n8k16.row.col.f32.bf16.bf16.f32 " \
        "{%0,%1,%2,%3}, {%4,%5,%6,%7}, {%8,%9}, {%0,%1,%2,%3};" \
        : "+f"((D)[0]), "+f"((D)[1]), "+f"((D)[2]), "+f"((D)[3]) \
        : "r"((A)[0]), "r"((A)[1]), "r"((A)[2]), "r"((A)[3]), \
          "r"((B)[0]), "r"((B)[1]))
#define CP_ASYNC16(dst, src) \
    asm volatile("cp.async.cg.shared.global [%0], [%1], 16;" \
        :: "r"(dst), "l"(src))
#define CP_COMMIT() asm volatile("cp.async.commit_group;")
#define CP_WAIT(N)  asm volatile("cp.async.wait_group %0;" :: "n"(N))

// ===========================================================================
// Fused prep: warp-per-row split+pack+sq  |  camid normalize + counter reset
// ===========================================================================
__global__ void prep_fused_kernel(const float* __restrict__ f,
                                  const int* __restrict__ cam_raw,
                                  int n, int d, int rowBlocks) {
    int b = blockIdx.x;
    if (b < rowBlocks) {
        int row  = b * 8 + (threadIdx.x >> 5);
        int lane = threadIdx.x & 31;
        if (row >= n) return;
        const float4* src = (const float4*)(f + (size_t)row * d) + lane * 2;
        float4 x0 = src[0], x1 = src[1];    // 8 elems
        float xv[8] = {x0.x, x0.y, x0.z, x0.w, x1.x, x1.y, x1.z, x1.w};
        float s = 0.f;
        uint32_t hu[4], lu[4];
#pragma unroll
        for (int q = 0; q < 4; ++q) {
            float a = xv[2 * q], c = xv[2 * q + 1];
            s += a * a + c * c;
            __nv_bfloat16 h0 = __float2bfloat16_rn(a);
            __nv_bfloat16 h1 = __float2bfloat16_rn(c);
            __nv_bfloat16 l0 = __float2bfloat16_rn(a - __bfloat162float(h0));
            __nv_bfloat16 l1 = __float2bfloat16_rn(c - __bfloat162float(h1));
            __nv_bfloat162 hh(h0, h1), ll(l0, l1);
            hu[q] = *(uint32_t*)&hh;
            lu[q] = *(uint32_t*)&ll;
        }
#pragma unroll
        for (int off = 16; off; off >>= 1) s += __shfl_down_sync(0xffffffffu, s, off);
        if (lane == 0) g_sq[row] = s;

        uint4 hv = make_uint4(hu[0], hu[1], hu[2], hu[3]);
        uint4 lv = make_uint4(lu[0], lu[1], lu[2], lu[3]);
        uint4* pa4 = (uint4*)(g_pa + (size_t)row * KPACK);
        uint4* pb4 = (uint4*)(g_pb + (size_t)row * KPACK);
        pa4[lane] = hv; pa4[32 + lane] = hv; pa4[64 + lane] = lv;
        pb4[lane] = hv; pb4[32 + lane] = lv; pb4[64 + lane] = hv;
    } else {
        __shared__ int s_is64;
        if (threadIdx.x == 0) {
            g_ctr = 0;
            int is64 = 1;
            int checks = n < 128 ? n : 128;
            for (int k = 0; k < checks; ++k)
                if (cam_raw[2 * k + 1] != 0) { is64 = 0; break; }
            s_is64 = is64;
        }
        __syncthreads();
        int is64 = s_is64;
        for (int j = threadIdx.x; j < n; j += blockDim.x)
            g_cam[j] = (unsigned char)(is64 ? cam_raw[2 * j] : cam_raw[j]);
    }
}

// ===========================================================================
// Distance GEMM via mma.sync bf16, UPPER-TRIANGLE blocks only (exact
// symmetry of hi.hi + hi.lo + lo.hi), mirror tile written via smem staging.
// 128x128 tile/CTA, 8 warps of 64x32. K=768, 12 chunks of 64,
// 3-stage cp.async pipeline, SW128 swizzle + ldmatrix.
// ===========================================================================
#define NCHUNK (KPACK / 64)
#define BUF_BYTES 32768                    // A 16KB + B 16KB
#define TLDA 129                           // f32 tile staging leading dim
#define SMEM_GEMM_TOTAL (1024 + 3 * BUF_BYTES)   // 99328; staging fits inside

__global__ void __launch_bounds__(256) dist_gemm_mma(int n) {
    extern __shared__ char smem_raw[];
    uint32_t sraw = smem_to_u32(smem_raw);
    uint32_t sbase = (sraw + 1023) & ~1023u;   // 1KB align for swizzle
    int tid = threadIdx.x, lane = tid & 31, wid = tid >> 5;

    // triangular decode: block t -> (bi, bj), bi <= bj
    int NB = n >> 7;
    int t = blockIdx.x;
    int bi = (int)((2.0f * NB + 1.0f -
                    sqrtf((2.0f * NB + 1.0f) * (2.0f * NB + 1.0f) - 8.0f * t)) * 0.5f);
    if (bi < 0) bi = 0;
    if (bi > NB - 1) bi = NB - 1;
#define TRI_START(r) ((r) * NB - ((r) * ((r) - 1)) / 2)
    while (bi + 1 < NB && TRI_START(bi + 1) <= t) ++bi;
    while (bi > 0 && TRI_START(bi) > t) --bi;
    int bj = bi + (t - TRI_START(bi));
#undef TRI_START

    const char* pa = (const char*)(g_pa + (size_t)bi * 128 * KPACK);
    const char* pb = (const char*)(g_pb + (size_t)bj * 128 * KPACK);
    const int ROWB = KPACK * 2;                // 1536 bytes per gmem row

    int seg = tid & 7, r0 = tid >> 3;

#define LOAD_CHUNK(c, buf) do { \
    uint32_t abase_ = sbase + (buf) * BUF_BYTES; \
    uint32_t bbase_ = abase_ + 16384; \
    _Pragma("unroll") \
    for (int it = 0; it < 4; ++it) { \
        int row = r0 + it * 32; \
        uint32_t off = row * 128 + seg * 16; \
        off = off ^ ((off >> 3) & 0x70); \
        CP_ASYNC16(abase_ + off, pa + (size_t)row * ROWB + (c) * 128 + seg * 16); \
        CP_ASYNC16(bbase_ + off, pb + (size_t)row * ROWB + (c) * 128 + seg * 16); \
    } \
    CP_COMMIT(); \
} while (0)

    int wr = wid >> 2, wc = wid & 3;
    int wm = wr * 64, wn = wc * 32;

    float acc[4][4][4];
#pragma unroll
    for (int mt = 0; mt < 4; ++mt)
#pragma unroll
        for (int nt = 0; nt < 4; ++nt)
#pragma unroll
            for (int e = 0; e < 4; ++e) acc[mt][nt][e] = 0.f;

    LOAD_CHUNK(0, 0);
    LOAD_CHUNK(1, 1);
    for (int c = 0; c < NCHUNK; ++c) {
        if (c == NCHUNK - 1) CP_WAIT(0);
        else                 CP_WAIT(1);       // chunk c complete
        __syncthreads();                       // data visible; prev compute done
        if (c + 2 < NCHUNK) LOAD_CHUNK(c + 2, (c + 2) % 3);

        uint32_t abase = sbase + (c % 3) * BUF_BYTES;
        uint32_t bbase = abase + 16384;
#pragma unroll
        for (int kk = 0; kk < 4; ++kk) {
            uint32_t afr[4][4], bfr[4][2];
#pragma unroll
            for (int mt = 0; mt < 4; ++mt) {
                int row = wm + mt * 16 + (lane & 15);
                uint32_t off = row * 128 + kk * 32 + (lane >> 4) * 16;
                off = off ^ ((off >> 3) & 0x70);
                LDMATRIX_X4(afr[mt], abase + off);
            }
#pragma unroll
            for (int np = 0; np < 2; ++np) {   // x4: 2 n-tiles per load
                int row = wn + np * 16 + ((lane >> 4) << 3) + (lane & 7);
                uint32_t off = row * 128 + kk * 32 + (((lane >> 3) & 1) << 4);
                off = off ^ ((off >> 3) & 0x70);
                uint32_t q[4];
                LDMATRIX_X4(q, bbase + off);
                bfr[np * 2 + 0][0] = q[0]; bfr[np * 2 + 0][1] = q[1];
                bfr[np * 2 + 1][0] = q[2]; bfr[np * 2 + 1][1] = q[3];
            }
#pragma unroll
            for (int mt = 0; mt < 4; ++mt)
#pragma unroll
                for (int nt = 0; nt < 4; ++nt)
                    MMA_BF16(acc[mt][nt], afr[mt], bfr[nt]);
        }
    }

    // ---- epilogue ----
    __shared__ float ssq[256];
    float* s_tile = (float*)(smem_raw + (sbase - sraw));
    if (tid < 128) ssq[tid] = g_sq[bi * 128 + tid];
    else           ssq[tid] = g_sq[bj * 128 + (tid - 128)];
    __syncthreads();   // all warps done with mainloop smem before s_tile reuse

    int g4 = lane >> 2, t4 = lane & 3;
#pragma unroll
    for (int mt = 0; mt < 4; ++mt) {
#pragma unroll
        for (int half = 0; half < 2; ++half) {
            int r = wm + mt * 16 + g4 + half * 8;
            int gi = bi * 128 + r;
            float sqi = ssq[r];
#pragma unroll
            for (int nt = 0; nt < 4; ++nt) {
                int col = wn + nt * 8 + 2 * t4;
                int gj = bj * 128 + col;
                float2 o;
                float d0 = sqi + ssq[128 + col] + EPS_F
                           - 2.0f * acc[mt][nt][half * 2 + 0];
                float d1 = sqi + ssq[128 + col + 1] + EPS_F
                           - 2.0f * acc[mt][nt][half * 2 + 1];
                o.x = sqrtf(fmaxf(d0, 1e-12f));
                o.y = sqrtf(fmaxf(d1, 1e-12f));
                if (gi == gj)     o.x = sqrtf(EPS_F);
                if (gi == gj + 1) o.y = sqrtf(EPS_F);
                *(float2*)(g_dist + (size_t)gi * n + gj) = o;
                s_tile[r * TLDA + col]     = o.x;
                s_tile[r * TLDA + col + 1] = o.y;
            }
        }
    }

    // mirror block (bj, bi): coalesced store from staged tile
    if (bi != bj) {
        __syncthreads();
#pragma unroll
        for (int it = 0; it < 16; ++it) {
            int c = it * 8 + wid;                        // tile column
            float* orow = g_dist + (size_t)(bj * 128 + c) * n + bi * 128;
#pragma unroll
            for (int q = 0; q < 4; ++q) {
                int r = lane + q * 32;
                orow[r] = s_tile[r * TLDA + c];          // bank-conflict-free
            }
        }
    }
#undef LOAD_CHUNK
}

// ===========================================================================
// Per-row selection + logsumexp (registers + warp pop-merge + f16x2 exp)
// Last CTA (atomic counter) does the deterministic final reduction.
// ===========================================================================
#define INSERT7(t, val) do { \
    float _v = (val); \
    if (_v < t[6]) { \
        t[6] = _v; \
        _Pragma("unroll") \
        for (int _k = 6; _k > 0; --_k) { \
            float _a = t[_k-1], _b = t[_k]; \
            t[_k-1] = fminf(_a, _b); t[_k] = fmaxf(_a, _b); } \
    } } while (0)

__device__ __forceinline__ void warp_pop7(float t[7], int lane, float* out) {
#pragma unroll
    for (int r = 0; r < 7; ++r) {
        float bv = t[0]; int bl = lane;
#pragma unroll
        for (int off = 16; off; off >>= 1) {
            float ov = __shfl_down_sync(0xffffffffu, bv, off);
            int   ol = __shfl_down_sync(0xffffffffu, bl, off);
            if (ov < bv) { bv = ov; bl = ol; }
        }
        bv = __shfl_sync(0xffffffffu, bv, 0);
        bl = __shfl_sync(0xffffffffu, bl, 0);
        if (lane == bl) {
#pragma unroll
            for (int k = 0; k < 6; ++k) t[k] = t[k + 1];
            t[6] = INF_F;
        }
        if (lane == 0) out[r] = bv;
    }
}

__global__ void __launch_bounds__(256) row_kernel(int n, float* __restrict__ out) {
    __shared__ float s_pop[2][8][8];
    __shared__ float s_res[2][2];
    __shared__ float s_sum[2][8];
    __shared__ float s_red[256];
    __shared__ int   s_last;

    int i = blockIdx.x, tid = threadIdx.x;
    int wid = tid >> 5, lane = tid & 31;
    const float* drow = g_dist + (size_t)i * n;
    int mycam = g_cam[i];

    float v[16];
    bool  m[16];
#pragma unroll
    for (int w = 0; w < 4; ++w) {
        int j = tid * 4 + w * 1024;
        float4 f = *(const float4*)(drow + j);
        v[w * 4 + 0] = f.x; v[w * 4 + 1] = f.y;
        v[w * 4 + 2] = f.z; v[w * 4 + 3] = f.w;
        uchar4 cc = ((const uchar4*)g_cam)[j >> 2];
        m[w * 4 + 0] = (cc.x == mycam); m[w * 4 + 1] = (cc.y == mycam);
        m[w * 4 + 2] = (cc.z == mycam); m[w * 4 + 3] = (cc.w == mycam);
    }

    float ti[7], te[7];
#pragma unroll
    for (int k = 0; k < 7; ++k) { ti[k] = INF_F; te[k] = INF_F; }
#pragma unroll
    for (int k = 0; k < 16; ++k) {
        if (m[k]) INSERT7(ti, v[k]);
        else      INSERT7(te, v[k]);
    }

    warp_pop7(ti, lane, &s_pop[0][wid][0]);
    warp_pop7(te, lane, &s_pop[1][wid][0]);
    __syncthreads();

    if (wid < 2) {   // warp 0: intra (K=4), warp 1: inter (K=6)
        float u[7];
#pragma unroll
        for (int k = 0; k < 7; ++k) u[k] = (lane < 8) ? s_pop[wid][lane][k] : INF_F;
        int K = (wid == 0) ? 4 : 6;
        float d0 = INF_F, dK = INF_F;
#pragma unroll
        for (int r = 0; r < 7; ++r) {
            float bv = u[0]; int bl = lane;
#pragma unroll
            for (int off = 16; off; off >>= 1) {
                float ov = __shfl_down_sync(0xffffffffu, bv, off);
                int   ol = __shfl_down_sync(0xffffffffu, bl, off);
                if (ov < bv) { bv = ov; bl = ol; }
            }
            bv = __shfl_sync(0xffffffffu, bv, 0);
            bl = __shfl_sync(0xffffffffu, bl, 0);
            if (lane == bl) {
#pragma unroll
                for (int k = 0; k < 6; ++k) u[k] = u[k + 1];
                u[6] = INF_F;
            }
            if (r == 0) d0 = bv;
            if (r == K) dK = bv;
        }
        if (lane == 0) { s_res[wid][0] = d0; s_res[wid][1] = dK; }
    }
    __syncthreads();

    float dKi = s_res[0][1], dKe = s_res[1][1];
    float CI = L2E10 * dKi, CE = L2E10 * dKe;
    float si = 0.f, se = 0.f;
#pragma unroll
    for (int k = 0; k < 16; k += 2) {
        float sel0 = m[k]     ? dKi : dKe;
        float sel1 = m[k + 1] ? dKi : dKe;
        // arg = 10*log2(e)*(dK - v), clamped to <= 0; excluded/far -> -100 (f16 exp2 -> 0)
        float a0 = fmaf(-L2E10, v[k],     m[k]     ? CI : CE);
        float a1 = fmaf(-L2E10, v[k + 1], m[k + 1] ? CI : CE);
        a0 = (v[k]     >= sel0) ? fminf(a0, 0.f) : -100.f;
        a1 = (v[k + 1] >= sel1) ? fminf(a1, 0.f) : -100.f;
        __half2 h = h2exp2(__floats2half2_rn(a0, a1));   // one MUFU op, two exps
        float2 r2 = __half22float2(h);
        si += m[k]     ? r2.x : 0.f;  se += m[k]     ? 0.f : r2.x;
        si += m[k + 1] ? r2.y : 0.f;  se += m[k + 1] ? 0.f : r2.y;
    }
#pragma unroll
    for (int off = 16; off; off >>= 1) {
        si += __shfl_down_sync(0xffffffffu, si, off);
        se += __shfl_down_sync(0xffffffffu, se, off);
    }
    if (lane == 0) { s_sum[0][wid] = si; s_sum[1][wid] = se; }
    __syncthreads();

    if (tid == 0) {
        float Si = 0.f, Se = 0.f;
#pragma unroll
        for (int w = 0; w < 8; ++w) { Si += s_sum[0][w]; Se += s_sum[1][w]; }
        float d0i = s_res[0][0], d0e = s_res[1][0];
        float term_i = 0.f, term_e = 0.f;
        if (isfinite(dKi))
            term_i = fmaxf(SCALE_F * (d0i - dKi) + logf(Si) + 40.0f, 0.f);
        if (isfinite(dKe))
            term_e = fmaxf(SCALE_F * (d0e - dKe) + logf(Se) + 6.0f, 0.f);
        g_partial[i] = term_i + 0.5f * term_e;
        __threadfence();
        int old = atomicAdd(&g_ctr, 1);
        s_last = (old == n - 1);
    }
    __syncthreads();

    // last CTA: deterministic fixed-order final reduction
    if (s_last) {
        float s = 0.f;
        for (int j = tid; j < n; j += 256) s += g_partial[j];
        s_red[tid] = s;
        __syncthreads();
        for (int st = 128; st; st >>= 1) {
            if (tid < st) s_red[tid] += s_red[tid + st];
            __syncthreads();
        }
        if (tid == 0) { out[0] = s_red[0] / (float)n; g_ctr = 0; }
    }
}

// ===========================================================================
extern "C" void kernel_launch(void* const* d_in, const int* in_sizes, int n_in,
                              void* d_out, int out_size) {
    const float* feat = (const float*)d_in[0];
    const int*   cam  = (const int*)d_in[1];
    int n = in_sizes[1];
    int d = in_sizes[0] / n;
    int NB = n / 128;

    static int smem_set = 0;
    if (!smem_set) {
        cudaFuncSetAttribute(dist_gemm_mma,
                             cudaFuncAttributeMaxDynamicSharedMemorySize,
                             SMEM_GEMM_TOTAL);
        smem_set = 1;
    }

    int rowBlocks = (n + 7) / 8;                 // warp-per-row, 8 warps/block
    prep_fused_kernel<<<rowBlocks + 1, 256>>>(feat, cam, n, d, rowBlocks);
    dist_gemm_mma<<<NB * (NB + 1) / 2, 256, SMEM_GEMM_TOTAL>>>(n);
    row_kernel<<<n, 256>>>(n, (float*)d_out);
}